// round 4
// baseline (speedup 1.0000x reference)
#include <cuda_runtime.h>
#include <cstdint>

#define B_ROWS 16384
#define C_COLS 4096

// Scratch (allocation-free): scatter bins and per-row partial losses.
__device__ unsigned long long g_bins[B_ROWS];
__device__ float g_partial[B_ROWS];

// Kernel 1: zero the bins (must happen every replay for determinism).
__global__ void init_bins_kernel() {
    int i = blockIdx.x * blockDim.x + threadIdx.x;
    if (i < B_ROWS) g_bins[i] = 0ull;
}

// Kernel 2: deterministic last-write-wins scatter.
// Pack (j << 32) | float_bits(v[index[j]]) and atomicMax per bin.
// Highest j wins (serial-loop semantics). Untouched bins stay 0 -> value 0.0f.
// NOTE: index/target are int32 (JAX x64 disabled downcasts jnp.int64 -> int32).
__global__ void scatter_kernel(const int* __restrict__ index,
                               const float* __restrict__ v,
                               int v_n) {
    int j = blockIdx.x * blockDim.x + threadIdx.x;
    if (j >= B_ROWS) return;
    unsigned idx = (unsigned)index[j];
    // Sanitize so a dtype surprise yields a wrong answer, not a fault.
    if (idx >= (unsigned)v_n) idx = 0u;
    unsigned pos = idx & (B_ROWS - 1);  // B_ROWS is a power of two
    unsigned vb = __float_as_uint(v[idx]);
    unsigned long long packed =
        ((unsigned long long)(unsigned)j << 32) | (unsigned long long)vb;
    atomicMax(&g_bins[pos], packed);
}

// Kernel 3: per-row weighted cross-entropy. One block per row, 128 threads.
// Early-exit rows with zero weight (skips the 16KB row read entirely).
__global__ void __launch_bounds__(128) loss_kernel(const float* __restrict__ input,
                                                   const int* __restrict__ target) {
    const int row = blockIdx.x;
    const int tid = threadIdx.x;

    // Weight for this row from the scatter result.
    const float w = __uint_as_float((unsigned)(g_bins[row] & 0xffffffffull));
    if (w == 0.0f) {
        if (tid == 0) g_partial[row] = 0.0f;
        return;
    }

    const float4* rowp = (const float4*)(input + (size_t)row * C_COLS);

    // Online (streaming) logsumexp per thread.
    float m = -3.402823466e38f;  // -FLT_MAX
    float s = 0.0f;
#pragma unroll
    for (int i = tid; i < C_COLS / 4; i += 128) {
        float4 x = rowp[i];
        float mx = fmaxf(fmaxf(x.x, x.y), fmaxf(x.z, x.w));
        if (mx > m) {
            s *= __expf(m - mx);
            m = mx;
        }
        s += __expf(x.x - m) + __expf(x.y - m) + __expf(x.z - m) + __expf(x.w - m);
    }

    // Warp-level (m, s) reduction.
#pragma unroll
    for (int off = 16; off > 0; off >>= 1) {
        float om = __shfl_xor_sync(0xffffffffu, m, off);
        float os = __shfl_xor_sync(0xffffffffu, s, off);
        float nm = fmaxf(m, om);
        s = s * __expf(m - nm) + os * __expf(om - nm);
        m = nm;
    }

    // Cross-warp combine (4 warps).
    __shared__ float sh_m[4];
    __shared__ float sh_s[4];
    const int warp = tid >> 5;
    const int lane = tid & 31;
    if (lane == 0) {
        sh_m[warp] = m;
        sh_s[warp] = s;
    }
    __syncthreads();

    if (tid == 0) {
        float M = sh_m[0];
        float S = sh_s[0];
#pragma unroll
        for (int k = 1; k < 4; k++) {
            float om = sh_m[k], os = sh_s[k];
            float nm = fmaxf(M, om);
            S = S * __expf(M - nm) + os * __expf(om - nm);
            M = nm;
        }
        unsigned t = (unsigned)target[row];
        if (t >= (unsigned)C_COLS) t = 0u;  // sanitize, never fault
        float xt = input[(size_t)row * C_COLS + (size_t)t];
        float loss = (logf(S) + M - xt);
        g_partial[row] = loss * w;
    }
}

// Kernel 4: deterministic single-block final reduction + mean.
__global__ void __launch_bounds__(256) reduce_kernel(float* __restrict__ out) {
    __shared__ float sh[256];
    float s = 0.0f;
    for (int i = threadIdx.x; i < B_ROWS; i += 256) s += g_partial[i];
    sh[threadIdx.x] = s;
    __syncthreads();
#pragma unroll
    for (int k = 128; k > 0; k >>= 1) {
        if (threadIdx.x < k) sh[threadIdx.x] += sh[threadIdx.x + k];
        __syncthreads();
    }
    if (threadIdx.x == 0) out[0] = sh[0] / (float)B_ROWS;
}

extern "C" void kernel_launch(void* const* d_in, const int* in_sizes, int n_in,
                              void* d_out, int out_size) {
    const float* input  = (const float*)d_in[0];  // [16384, 4096] f32
    const float* v      = (const float*)d_in[1];  // [1000000] f32
    const int*   target = (const int*)d_in[2];    // [16384] i32 (x64-disabled JAX)
    const int*   index  = (const int*)d_in[3];    // [16384] i32
    float* out = (float*)d_out;
    const int v_n = in_sizes[1];

    init_bins_kernel<<<(B_ROWS + 255) / 256, 256>>>();
    scatter_kernel<<<(B_ROWS + 255) / 256, 256>>>(index, v, v_n);
    loss_kernel<<<B_ROWS, 128>>>(input, target);
    reduce_kernel<<<1, 256>>>(out);
}